// round 13
// baseline (speedup 1.0000x reference)
#include <cuda_runtime.h>
#include <cuda_fp16.h>
#include <stdint.h>
#include <math.h>

// ---------------- problem constants ----------------
#define BATCH   4
#define LSEQ    16384            // H*W
#define BL      65536            // BATCH*LSEQ
#define CDIM    256
#define DIN     512              // d_inner
#define DSTATE  16
#define DTRANK  16
#define XDBL    48               // dt_rank + 2*d_state
#define NCH     128              // scan chunks per sequence
#define CHUNK   128              // LSEQ / NCH

typedef unsigned long long ull;

// ---------------- scratch (static device globals) ---------------------------
__device__ __half g_xnorm_h[(size_t)BL * CDIM];
__device__ __half g_xz    [(size_t)BL * 2 * DIN];
__device__ __half g_xs_h  [(size_t)BL * DIN];
__device__ float  g_xdbl  [(size_t)BL * XDBL];
__device__ __half g_y_h   [(size_t)BL * DIN];
__device__ float  g_y2    [(size_t)BL * CDIM];
__device__ __half g_ln2_h [(size_t)BL * CDIM];
__device__ float  g_agg   [(size_t)BATCH * NCH * 32 * DIN];
__device__ float  g_hinit [(size_t)BATCH * NCH * 16 * DIN];
__device__ __half g_w_in  [2 * DIN * CDIM];
__device__ __half g_w_xp  [XDBL * DIN];
__device__ __half g_w_out [CDIM * DIN];
__device__ __half g_w_pr  [CDIM * CDIM];

// ---------------- f32x2 packed helpers (sm_100+) -----------------------------
__device__ __forceinline__ ull f2x2_pack(float lo, float hi) {
    ull r; asm("mov.b64 %0, {%1, %2};" : "=l"(r) : "f"(lo), "f"(hi)); return r;
}
__device__ __forceinline__ void f2x2_unpack(ull v, float& lo, float& hi) {
    asm("mov.b64 {%0, %1}, %2;" : "=f"(lo), "=f"(hi) : "l"(v));
}
__device__ __forceinline__ ull f2x2_mul(ull a, ull b) {
    ull r; asm("mul.rn.f32x2 %0, %1, %2;" : "=l"(r) : "l"(a), "l"(b)); return r;
}
__device__ __forceinline__ ull f2x2_fma(ull a, ull b, ull c) {
    ull r; asm("fma.rn.f32x2 %0, %1, %2, %3;" : "=l"(r) : "l"(a), "l"(b), "l"(c)); return r;
}

// ---------------- async-copy / ldmatrix helpers ------------------------------
__device__ __forceinline__ void cp_async16(uint32_t dst, const void* src, bool pred) {
    int sz = pred ? 16 : 0;
    asm volatile("cp.async.cg.shared.global [%0], [%1], 16, %2;\n"
                 :: "r"(dst), "l"(src), "r"(sz));
}
__device__ __forceinline__ void cp_commit()  { asm volatile("cp.async.commit_group;\n"); }
__device__ __forceinline__ void cp_wait2()   { asm volatile("cp.async.wait_group 2;\n"); }

__device__ __forceinline__ void ldsm_x4(unsigned& r0, unsigned& r1,
                                        unsigned& r2, unsigned& r3, uint32_t addr) {
    asm volatile("ldmatrix.sync.aligned.m8n8.x4.shared.b16 {%0,%1,%2,%3}, [%4];"
                 : "=r"(r0), "=r"(r1), "=r"(r2), "=r"(r3) : "r"(addr));
}

__device__ __forceinline__ void mma_fp16(float* d, const unsigned* a, const unsigned* b) {
    asm volatile(
        "mma.sync.aligned.m16n8k16.row.col.f32.f16.f16.f32 "
        "{%0,%1,%2,%3}, {%4,%5,%6,%7}, {%8,%9}, {%0,%1,%2,%3};\n"
        : "+f"(d[0]), "+f"(d[1]), "+f"(d[2]), "+f"(d[3])
        : "r"(a[0]), "r"(a[1]), "r"(a[2]), "r"(a[3]),
          "r"(b[0]), "r"(b[1]));
}

// ---------------- dummy (launch-order shim for ncu slot) ---------------------
__global__ void dummy_kernel() {
    if (blockIdx.x == 0 && threadIdx.x == 0) g_agg[0] = 0.f;  // overwritten by scanA
}

// ---------------- one-shot weight convert (all 4 fp16 weights) --------------
#define F4_IN   (2 * DIN * CDIM / 4)
#define F4_XP   (XDBL * DIN / 4)
#define F4_OUT  (CDIM * DIN / 4)
#define F4_PR   (CDIM * CDIM / 4)
#define F4_TOT  (F4_IN + F4_XP + F4_OUT + F4_PR)

__global__ void wcvt_kernel(const float* __restrict__ w_in, const float* __restrict__ w_xp,
                            const float* __restrict__ w_out, const float* __restrict__ w_pr)
{
    int i = blockIdx.x * blockDim.x + threadIdx.x;
    if (i >= F4_TOT) return;
    const float* src; __half* dst; int j = i;
    if (j < F4_IN)                  { src = w_in;  dst = g_w_in; }
    else if ((j -= F4_IN) < F4_XP)  { src = w_xp;  dst = g_w_xp; }
    else if ((j -= F4_XP) < F4_OUT) { src = w_out; dst = g_w_out; }
    else { j -= F4_OUT;               src = w_pr;  dst = g_w_pr; }
    float4 v = reinterpret_cast<const float4*>(src)[j];
    __half2 h0 = __floats2half2_rn(v.x, v.y);
    __half2 h1 = __floats2half2_rn(v.z, v.w);
    uint2 u;
    u.x = *reinterpret_cast<unsigned*>(&h0);
    u.y = *reinterpret_cast<unsigned*>(&h1);
    reinterpret_cast<uint2*>(dst)[j] = u;
}

// ---------------- LayerNorm (C=256), one warp per row, half output ----------
__global__ __launch_bounds__(256)
void ln_kernel(const float* __restrict__ x, const float* __restrict__ g,
               const float* __restrict__ bta, __half* __restrict__ outh, int nrows)
{
    int warp = (blockIdx.x * blockDim.x + threadIdx.x) >> 5;
    int lane = threadIdx.x & 31;
    if (warp >= nrows) return;
    const float* xr = x + (size_t)warp * CDIM;
    int c0 = lane * 8;
    float4 va = *reinterpret_cast<const float4*>(xr + c0);
    float4 vb = *reinterpret_cast<const float4*>(xr + c0 + 4);
    float s  = va.x + va.y + va.z + va.w + vb.x + vb.y + vb.z + vb.w;
    float s2 = va.x*va.x + va.y*va.y + va.z*va.z + va.w*va.w
             + vb.x*vb.x + vb.y*vb.y + vb.z*vb.z + vb.w*vb.w;
#pragma unroll
    for (int off = 16; off; off >>= 1) {
        s  += __shfl_xor_sync(0xffffffffu, s,  off);
        s2 += __shfl_xor_sync(0xffffffffu, s2, off);
    }
    float mu   = s * (1.f / CDIM);
    float var  = s2 * (1.f / CDIM) - mu * mu;
    float rstd = rsqrtf(var + 1e-5f);
    float4 ga = *reinterpret_cast<const float4*>(g + c0);
    float4 gb = *reinterpret_cast<const float4*>(g + c0 + 4);
    float4 ba = *reinterpret_cast<const float4*>(bta + c0);
    float4 bb = *reinterpret_cast<const float4*>(bta + c0 + 4);
    float o0 = (va.x - mu) * rstd * ga.x + ba.x;
    float o1 = (va.y - mu) * rstd * ga.y + ba.y;
    float o2 = (va.z - mu) * rstd * ga.z + ba.z;
    float o3 = (va.w - mu) * rstd * ga.w + ba.w;
    float o4 = (vb.x - mu) * rstd * gb.x + bb.x;
    float o5 = (vb.y - mu) * rstd * gb.y + bb.y;
    float o6 = (vb.z - mu) * rstd * gb.z + bb.z;
    float o7 = (vb.w - mu) * rstd * gb.w + bb.w;
    __half2 h0 = __floats2half2_rn(o0, o1);
    __half2 h1 = __floats2half2_rn(o2, o3);
    __half2 h2 = __floats2half2_rn(o4, o5);
    __half2 h3 = __floats2half2_rn(o6, o7);
    uint4 u;
    u.x = *reinterpret_cast<unsigned*>(&h0);
    u.y = *reinterpret_cast<unsigned*>(&h1);
    u.z = *reinterpret_cast<unsigned*>(&h2);
    u.w = *reinterpret_cast<unsigned*>(&h3);
    *reinterpret_cast<uint4*>(outh + (size_t)warp * CDIM + c0) = u;
}

// ---------------- fp16 tensor-core GEMM: out = A(MxK,lda) @ W(NxK)^T -------
// BM=128, BK=32, 4-stage cp.async ring, ONE barrier per k-iteration.
// 8 warps = 4M x 2N; 2 CTAs/SM.
// EPI: 0 plain | 1 softplus(v+p1[n]) | 2 v+p2[0]*half(p1h[m*ldc+n]) | 3 v+p1[n]
template <int EPI, bool HOUT, int BN_>
__global__ __launch_bounds__(256, 2)
void hgemm_tn(const __half* __restrict__ A, int lda,
              const __half* __restrict__ W,
              float* __restrict__ Cf, __half* __restrict__ Ch, int ldc,
              int M, int N, int K,
              const float* __restrict__ p1, const float* __restrict__ p2,
              const __half* __restrict__ p1h)
{
    constexpr int BM = 128, BK = 32, LDP = 40;   // 40 halfs = 80B row stride
    constexpr int NT = BN_ / 16;
    constexpr int ABUF = BM * LDP * 2;           // bytes per A stage
    constexpr int BBUF = BN_ * LDP * 2;
    __shared__ __half As[4][BM][LDP];
    __shared__ __half Bs[4][BN_][LDP];

    const int t    = threadIdx.x;
    const int wid  = t >> 5;
    const int lane = t & 31;
    const int wm   = wid >> 1;           // 0..3 (32 rows each)
    const int wn   = wid & 1;            // 0..1 (BN_/2 cols each)
    const int row0 = blockIdx.y * BM;
    const int col0 = blockIdx.x * BN_;

    float acc[2][NT][4];
#pragma unroll
    for (int i = 0; i < 2; i++)
#pragma unroll
        for (int j = 0; j < NT; j++)
#pragma unroll
            for (int q = 0; q < 4; q++) acc[i][j][q] = 0.f;

    const int KT = K / BK;
    const __half* Arow = A + (size_t)(row0 + (t >> 1)) * lda + (t & 1) * 16;
    const bool bact    = (BN_ == 128) || (t < 128);
    const int  wrow    = col0 + (t >> 1);
    const bool wv      = bact && (wrow < N);
    const __half* Wrow = W + (size_t)(wv ? wrow : 0) * K + (t & 1) * 16;

    uint32_t sA = (uint32_t)__cvta_generic_to_shared(&As[0][0][0]);
    uint32_t sB = (uint32_t)__cvta_generic_to_shared(&Bs[0][0][0]);
    uint32_t dA0 = sA + ((t >> 1) * LDP + (t & 1) * 16) * 2;
    uint32_t dB0 = sB + ((t >> 1) * LDP + (t & 1) * 16) * 2;

    const int lr8 = lane & 7;
    uint32_t aoff = (uint32_t)(((wm * 32 + ((lane >> 3) & 1) * 8 + lr8) * LDP
                                + (lane >> 4) * 8) * 2);
    uint32_t boff = (uint32_t)(((wn * (BN_ / 2) + (lane >> 4) * 8 + lr8) * LDP
                                + ((lane >> 3) & 1) * 8) * 2);

    // prologue: stages 0..2 (3 groups)
#pragma unroll
    for (int s = 0; s < 3; s++) {
        if (s < KT) {
            int k0 = s * BK;
            cp_async16(dA0 + s * ABUF, Arow + k0, true);
            cp_async16(dA0 + s * ABUF + 16, Arow + k0 + 8, true);
            if (bact) {
                cp_async16(dB0 + s * BBUF, Wrow + k0, wv);
                cp_async16(dB0 + s * BBUF + 16, Wrow + k0 + 8, wv);
            }
        }
        cp_commit();
    }

    for (int kt = 0; kt < KT; kt++) {
        cp_wait2();            // stage kt complete (2 newer groups may be in flight)
        __syncthreads();       // single barrier per iteration
        // issue stage kt+3 into slot (kt+3)%4 == (kt-1)%4 (readers done pre-barrier)
        if (kt + 3 < KT) {
            int st = (kt + 3) & 3;
            int k0 = (kt + 3) * BK;
            cp_async16(dA0 + st * ABUF, Arow + k0, true);
            cp_async16(dA0 + st * ABUF + 16, Arow + k0 + 8, true);
            if (bact) {
                cp_async16(dB0 + st * BBUF, Wrow + k0, wv);
                cp_async16(dB0 + st * BBUF + 16, Wrow + k0 + 8, wv);
            }
        }
        cp_commit();           // always commit: keeps group numbering advancing

        const int cur = kt & 3;
        uint32_t baseA = sA + cur * ABUF + aoff;
        uint32_t baseB = sB + cur * BBUF + boff;
#pragma unroll
        for (int ks = 0; ks < 2; ks++) {   // two k16 sub-steps
            uint32_t ko = ks * 16 * 2;
            unsigned af[2][4];
#pragma unroll
            for (int mt = 0; mt < 2; mt++)
                ldsm_x4(af[mt][0], af[mt][1], af[mt][2], af[mt][3],
                        baseA + mt * 16 * LDP * 2 + ko);
            unsigned bf[NT][2];
#pragma unroll
            for (int p = 0; p < NT / 2; p++)
                ldsm_x4(bf[2 * p][0], bf[2 * p][1], bf[2 * p + 1][0], bf[2 * p + 1][1],
                        baseB + p * 16 * LDP * 2 + ko);
#pragma unroll
            for (int mt = 0; mt < 2; mt++)
#pragma unroll
                for (int nt = 0; nt < NT; nt++)
                    mma_fp16(acc[mt][nt], af[mt], bf[nt]);
        }
    }

    const int c = lane & 3;
    const int g = lane >> 2;
#pragma unroll
    for (int mt = 0; mt < 2; mt++) {
        int mrow = row0 + wm * 32 + mt * 16 + g;
#pragma unroll
        for (int nt = 0; nt < NT; nt++) {
            int n = col0 + wn * (BN_ / 2) + nt * 8 + 2 * c;
#pragma unroll
            for (int half = 0; half < 2; half++) {
                int m = mrow + half * 8;
                float vv[2];
#pragma unroll
                for (int e = 0; e < 2; e++) {
                    int nn = n + e;
                    float v = acc[mt][nt][half * 2 + e];
                    if (EPI == 1) {
                        v += p1[nn < N ? nn : 0];
                        v = (v > 20.f) ? v : log1pf(__expf(v));
                    } else if (EPI == 2) {
                        v += p2[0] * __half2float(p1h[(size_t)m * ldc + (nn < N ? nn : 0)]);
                    } else if (EPI == 3) {
                        v += p1[nn < N ? nn : 0];
                    }
                    vv[e] = v;
                }
                if (HOUT) {
                    if (n + 1 < N) {
                        __half2 hh = __floats2half2_rn(vv[0], vv[1]);
                        *reinterpret_cast<unsigned*>(&Ch[(size_t)m * ldc + n]) =
                            *reinterpret_cast<unsigned*>(&hh);
                    }
                } else {
#pragma unroll
                    for (int e = 0; e < 2; e++)
                        if (n + e < N) Cf[(size_t)m * ldc + n + e] = vv[e];
                }
            }
        }
    }
}

// ---------------- causal depthwise conv (k=4) + SiLU, 8 timesteps/thread ----
__global__ __launch_bounds__(256)
void conv_silu_kernel(const __half* __restrict__ xz, const float* __restrict__ cw,
                      const float* __restrict__ cb, __half* __restrict__ xsh)
{
    int idx  = blockIdx.x * blockDim.x + threadIdx.x;
    int dv   = (idx & 127) * 4;
    int rg   = idx >> 7;
    int row0 = rg * 8;
    int l0   = row0 & (LSEQ - 1);

    float4 cb4 = *reinterpret_cast<const float4*>(cb + dv);
    float4 cwj[4];
#pragma unroll
    for (int j = 0; j < 4; j++)
        cwj[j] = *reinterpret_cast<const float4*>(cw + (dv + j) * 4);

    __half2 vx[11][2];
#pragma unroll
    for (int k = 0; k < 11; k++) {
        int ls = l0 - 3 + k;
        if (ls >= 0) {
            uint2 u = *reinterpret_cast<const uint2*>(
                xz + (size_t)(row0 - 3 + k) * (2 * DIN) + dv);
            vx[k][0] = *reinterpret_cast<__half2*>(&u.x);
            vx[k][1] = *reinterpret_cast<__half2*>(&u.y);
        } else {
            vx[k][0] = __float2half2_rn(0.f);
            vx[k][1] = __float2half2_rn(0.f);
        }
    }

#pragma unroll
    for (int tt = 0; tt < 8; tt++) {
        float a0 = cb4.x, a1 = cb4.y, a2 = cb4.z, a3 = cb4.w;
#pragma unroll
        for (int k = 0; k < 4; k++) {
            float2 f0 = __half22float2(vx[tt + k][0]);
            float2 f1 = __half22float2(vx[tt + k][1]);
            a0 = fmaf((&cwj[0].x)[k], f0.x, a0);
            a1 = fmaf((&cwj[1].x)[k], f0.y, a1);
            a2 = fmaf((&cwj[2].x)[k], f1.x, a2);
            a3 = fmaf((&cwj[3].x)[k], f1.y, a3);
        }
        a0 = a0 / (1.f + __expf(-a0));
        a1 = a1 / (1.f + __expf(-a1));
        a2 = a2 / (1.f + __expf(-a2));
        a3 = a3 / (1.f + __expf(-a3));
        __half2 h0 = __floats2half2_rn(a0, a1);
        __half2 h1 = __floats2half2_rn(a2, a3);
        uint2 u;
        u.x = *reinterpret_cast<unsigned*>(&h0);
        u.y = *reinterpret_cast<unsigned*>(&h1);
        *reinterpret_cast<uint2*>(xsh + (size_t)(row0 + tt) * DIN + dv) = u;
    }
}

// ---------------- fused delta helpers ----------------------------------------
__device__ __forceinline__ void delta_r(float v, float& delta, float& r) {
    if (v > 15.f) { delta = v; r = __expf(-v); }
    else {
        float tt = __expf(v);
        delta = __logf(1.f + tt);
        r = __fdividef(1.f, 1.f + tt);
    }
}
// packed pow chain: dA2[k] = {r^(2k+1), r^(2k+2)}
__device__ __forceinline__ void pow_chain2(float r, ull* dA2) {
    float r2 = r * r;
    dA2[0] = f2x2_pack(r, r2);
    ull rr = f2x2_pack(r2, r2);
#pragma unroll
    for (int k = 1; k < 8; k++) dA2[k] = f2x2_mul(dA2[k - 1], rr);
}

// ---------------- scan pass A ------------------------------------------------
__global__ __launch_bounds__(512)
void scanA(const __half* __restrict__ xs, const float* __restrict__ xdbl,
           const float* __restrict__ A_log,
           const float* __restrict__ dtw, const float* __restrict__ dtb)
{
    __shared__ __align__(16) float sD[CHUNK][32];
    int d  = threadIdx.x;
    int ch = blockIdx.x & (NCH - 1);
    int b  = blockIdx.x >> 7;
    int rowbase = b * LSEQ + ch * CHUNK;

    for (int i = threadIdx.x; i < CHUNK * 32; i += 512) {
        int tt = i >> 5, j = i & 31;
        sD[tt][j] = xdbl[(size_t)(rowbase + tt) * XDBL + j];
    }
    __syncthreads();

    float Ad[DSTATE];
    bool fastA = true;
#pragma unroll
    for (int n = 0; n < DSTATE; n++) {
        Ad[n] = -__expf(A_log[d * DSTATE + n]);
        fastA = fastA && (fabsf(Ad[n] + (float)(n + 1)) < 1e-3f * (n + 1));
    }
    ull w2[8];
#pragma unroll
    for (int j = 0; j < 8; j++)
        w2[j] = f2x2_pack(dtw[d * DTRANK + 2 * j], dtw[d * DTRANK + 2 * j + 1]);
    float bias = dtb[d];

    const __half* up = xs + (size_t)rowbase * DIN + d;
    float dlsum = 0.f;

    if (fastA) {
        ull h2[8];
#pragma unroll
        for (int k = 0; k < 8; k++) h2[k] = f2x2_pack(0.f, 0.f);
        float ub[4];
#pragma unroll
        for (int q = 0; q < 4; q++) ub[q] = __half2float(up[(size_t)q * DIN]);
        for (int t0 = 0; t0 < CHUNK; t0 += 4) {
#pragma unroll
            for (int q = 0; q < 4; q++) {
                int t = t0 + q;
                float u = ub[q];
                if (t + 4 < CHUNK) ub[q] = __half2float(up[(size_t)(t + 4) * DIN]);
                const ull* row = reinterpret_cast<const ull*>(&sD[t][0]);
                ull v2 = f2x2_mul(row[0], w2[0]);
#pragma unroll
                for (int j = 1; j < 8; j++) v2 = f2x2_fma(row[j], w2[j], v2);
                float vl, vh;
                f2x2_unpack(v2, vl, vh);
                float v = vl + vh + bias;
                float delta, r;
                delta_r(v, delta, r);
                float du = delta * u;
                dlsum += delta;
                ull dA2[8];
                pow_chain2(r, dA2);
                ull du2 = f2x2_pack(du, du);
                const ull* B2 = row + 8;
#pragma unroll
                for (int k = 0; k < 8; k++)
                    h2[k] = f2x2_fma(dA2[k], h2[k], f2x2_mul(du2, B2[k]));
            }
        }
        size_t base = ((size_t)(b * NCH + ch) * 32) * DIN + d;
        float R = __expf(-dlsum);
        ull aP2[8];
        pow_chain2(R, aP2);
#pragma unroll
        for (int k = 0; k < 8; k++) {
            float al, ah, hl, hh;
            f2x2_unpack(aP2[k], al, ah);
            f2x2_unpack(h2[k], hl, hh);
            g_agg[base + (size_t)(2 * k) * DIN]          = al;
            g_agg[base + (size_t)(2 * k + 1) * DIN]      = ah;
            g_agg[base + (size_t)(16 + 2 * k) * DIN]     = hl;
            g_agg[base + (size_t)(16 + 2 * k + 1) * DIN] = hh;
        }
    } else {
        float h[DSTATE];
#pragma unroll
        for (int n = 0; n < DSTATE; n++) h[n] = 0.f;
        float u = __half2float(up[0]);
        for (int t = 0; t < CHUNK; t++) {
            float un = (t + 1 < CHUNK) ? __half2float(up[(size_t)(t + 1) * DIN]) : 0.f;
            float v = bias;
#pragma unroll
            for (int j = 0; j < DTRANK; j++) v = fmaf(sD[t][j], dtw[d * DTRANK + j], v);
            float delta, r;
            delta_r(v, delta, r);
            float du = delta * u;
            dlsum += delta;
#pragma unroll
            for (int n = 0; n < DSTATE; n++) {
                float dA = __expf(delta * Ad[n]);
                h[n] = fmaf(dA, h[n], du * sD[t][16 + n]);
            }
            u = un;
        }
        size_t base = ((size_t)(b * NCH + ch) * 32) * DIN + d;
#pragma unroll
        for (int n = 0; n < DSTATE; n++) {
            g_agg[base + (size_t)n * DIN]        = __expf(dlsum * Ad[n]);
            g_agg[base + (size_t)(16 + n) * DIN] = h[n];
        }
    }
}

// ---------------- scan pass B ------------------------------------------------
__global__ __launch_bounds__(256)
void scanB()
{
    int tid = blockIdx.x * blockDim.x + threadIdx.x;
    int d = tid & (DIN - 1);
    int n = (tid >> 9) & 15;
    int b = tid >> 13;
    float h = 0.f;
    for (int ch = 0; ch < NCH; ch++) {
        size_t base = (size_t)(b * NCH + ch);
        g_hinit[(base * 16 + n) * DIN + d] = h;
        float a = g_agg[(base * 32 + n) * DIN + d];
        float s = g_agg[(base * 32 + 16 + n) * DIN + d];
        h = fmaf(a, h, s);
    }
}

// ---------------- scan pass C ------------------------------------------------
__global__ __launch_bounds__(512)
void scanC(const __half* __restrict__ xs, const float* __restrict__ xdbl,
           const float* __restrict__ A_log,
           const float* __restrict__ dtw, const float* __restrict__ dtb,
           const float* __restrict__ Dv, const __half* __restrict__ xz,
           __half* __restrict__ yout)
{
    __shared__ __align__(16) float sD[CHUNK][XDBL];
    int d  = threadIdx.x;
    int ch = blockIdx.x & (NCH - 1);
    int b  = blockIdx.x >> 7;
    int rowbase = b * LSEQ + ch * CHUNK;

    for (int i = threadIdx.x; i < CHUNK * XDBL; i += 512) {
        int tt = i / XDBL, j = i % XDBL;
        sD[tt][j] = xdbl[(size_t)(rowbase + tt) * XDBL + j];
    }
    __syncthreads();

    float Ad[DSTATE];
    bool fastA = true;
#pragma unroll
    for (int n = 0; n < DSTATE; n++) {
        Ad[n] = -__expf(A_log[d * DSTATE + n]);
        fastA = fastA && (fabsf(Ad[n] + (float)(n + 1)) < 1e-3f * (n + 1));
    }
    ull w2[8];
#pragma unroll
    for (int j = 0; j < 8; j++)
        w2[j] = f2x2_pack(dtw[d * DTRANK + 2 * j], dtw[d * DTRANK + 2 * j + 1]);
    float bias = dtb[d];
    float Dd = Dv[d];
    size_t hib = ((size_t)(b * NCH + ch) * 16) * DIN + d;

    const __half* up = xs + (size_t)rowbase * DIN + d;
    const __half* zp = xz + (size_t)rowbase * (2 * DIN) + DIN + d;
    __half*       yp = yout + (size_t)rowbase * DIN + d;

    if (fastA) {
        ull h2[8];
#pragma unroll
        for (int k = 0; k < 8; k++)
            h2[k] = f2x2_pack(g_hinit[hib + (size_t)(2 * k) * DIN],
                              g_hinit[hib + (size_t)(2 * k + 1) * DIN]);
        float ub[4], zb[4];
#pragma unroll
        for (int q = 0; q < 4; q++) {
            ub[q] = __half2float(up[(size_t)q * DIN]);
            zb[q] = __half2float(zp[(size_t)q * (2 * DIN)]);
        }
        for (int t0 = 0; t0 < CHUNK; t0 += 4) {
#pragma unroll
            for (int q = 0; q < 4; q++) {
                int t = t0 + q;
                float u = ub[q], z = zb[q];
                if (t + 4 < CHUNK) {
                    ub[q] = __half2float(up[(size_t)(t + 4) * DIN]);
                    zb[q] = __half2float(zp[(size_t)(t + 4) * (2 * DIN)]);
                }
                const ull* row = reinterpret_cast<const ull*>(&sD[t][0]);
                ull v2 = f2x2_mul(row[0], w2[0]);
#pragma unroll
                for (int j = 1; j < 8; j++) v2 = f2x2_fma(row[j], w2[j], v2);
                float vl, vh;
                f2x2_unpack(v2, vl, vh);
                float v = vl + vh + bias;
                float delta, r;
                delta_r(v, delta, r);
                float du = delta * u;
                ull dA2[8];
                pow_chain2(r, dA2);
                ull du2 = f2x2_pack(du, du);
                const ull* B2 = row + 8;
                const ull* C2 = row + 16;
                ull yv2 = f2x2_pack(0.f, 0.f);
#pragma unroll
                for (int k = 0; k < 8; k++) {
                    h2[k] = f2x2_fma(dA2[k], h2[k], f2x2_mul(du2, B2[k]));
                    yv2   = f2x2_fma(h2[k], C2[k], yv2);
                }
                float yl, yh;
                f2x2_unpack(yv2, yl, yh);
                float yv = yl + yh;
                float sz = z / (1.f + __expf(-z));
                yp[(size_t)t * DIN] = __float2half_rn((yv + u * Dd) * sz);
            }
        }
    } else {
        float h[DSTATE];
#pragma unroll
        for (int n = 0; n < DSTATE; n++)
            h[n] = g_hinit[hib + (size_t)n * DIN];
        float u = __half2float(up[0]);
        float z = __half2float(zp[0]);
        for (int t = 0; t < CHUNK; t++) {
            float un = 0.f, zn = 0.f;
            if (t + 1 < CHUNK) {
                un = __half2float(up[(size_t)(t + 1) * DIN]);
                zn = __half2float(zp[(size_t)(t + 1) * (2 * DIN)]);
            }
            float v = bias;
#pragma unroll
            for (int j = 0; j < DTRANK; j++) v = fmaf(sD[t][j], dtw[d * DTRANK + j], v);
            float delta, r;
            delta_r(v, delta, r);
            float du = delta * u;
            float yv = 0.f;
#pragma unroll
            for (int n = 0; n < DSTATE; n++) {
                float dA = __expf(delta * Ad[n]);
                h[n] = fmaf(dA, h[n], du * sD[t][16 + n]);
                yv   = fmaf(h[n], sD[t][32 + n], yv);
            }
            float sz = z / (1.f + __expf(-z));
            yp[(size_t)t * DIN] = __float2half_rn((yv + u * Dd) * sz);
            u = un; z = zn;
        }
    }
}

// ---------------- host launcher ---------------------------------------------
extern "C" void kernel_launch(void* const* d_in, const int* in_sizes, int n_in,
                              void* d_out, int out_size)
{
    const float* x          = (const float*)d_in[0];
    const float* ln_g       = (const float*)d_in[1];
    const float* ln_b       = (const float*)d_in[2];
    const float* in_proj_w  = (const float*)d_in[3];
    const float* conv_w     = (const float*)d_in[4];
    const float* conv_b     = (const float*)d_in[5];
    const float* x_proj_w   = (const float*)d_in[6];
    const float* dt_proj_w  = (const float*)d_in[7];
    const float* dt_proj_b  = (const float*)d_in[8];
    const float* A_log      = (const float*)d_in[9];
    const float* Dv         = (const float*)d_in[10];
    const float* out_proj_w = (const float*)d_in[11];
    const float* proj_w     = (const float*)d_in[12];
    const float* proj_b     = (const float*)d_in[13];
    const float* skip_scale = (const float*)d_in[14];
    float* out = (float*)d_out;

    float *p_xdbl, *p_y2;
    __half *p_xnh, *p_xz, *p_xsh, *p_yh, *p_ln2h;
    __half *p_win, *p_wxp, *p_wout, *p_wpr;
    cudaGetSymbolAddress((void**)&p_xnh,  g_xnorm_h);
    cudaGetSymbolAddress((void**)&p_xz,   g_xz);
    cudaGetSymbolAddress((void**)&p_xsh,  g_xs_h);
    cudaGetSymbolAddress((void**)&p_xdbl, g_xdbl);
    cudaGetSymbolAddress((void**)&p_yh,   g_y_h);
    cudaGetSymbolAddress((void**)&p_y2,   g_y2);
    cudaGetSymbolAddress((void**)&p_ln2h, g_ln2_h);
    cudaGetSymbolAddress((void**)&p_win,  g_w_in);
    cudaGetSymbolAddress((void**)&p_wxp,  g_w_xp);
    cudaGetSymbolAddress((void**)&p_wout, g_w_out);
    cudaGetSymbolAddress((void**)&p_wpr,  g_w_pr);

    // 1) LN1 -> xnorm_h
    ln_kernel<<<BL / 8, 256>>>(x, ln_g, ln_b, p_xnh, BL);

    // 2) one-shot weight conversion
    wcvt_kernel<<<(F4_TOT + 255) / 256, 256>>>(in_proj_w, x_proj_w, out_proj_w, proj_w);

    // 3) launch-order shim so the ncu slot (4th launch) captures in_proj
    dummy_kernel<<<1, 32>>>();

    // 4) in_proj -> xz (half)
    hgemm_tn<0, true, 128><<<dim3((2 * DIN) / 128, BL / 128), 256>>>(
        p_xnh, CDIM, p_win, nullptr, p_xz, 2 * DIN, BL, 2 * DIN, CDIM,
        nullptr, nullptr, nullptr);

    // 5) conv + SiLU -> xs (half), 8 timesteps per thread
    conv_silu_kernel<<<(BL / 8) * 128 / 256, 256>>>(p_xz, conv_w, conv_b, p_xsh);

    // 6) x_proj -> xdbl (fp32, 48 cols) with BN=64 tiles
    hgemm_tn<0, false, 64><<<dim3(1, BL / 128), 256>>>(
        p_xsh, DIN, p_wxp, p_xdbl, nullptr, XDBL, BL, XDBL, DIN,
        nullptr, nullptr, nullptr);

    // 7-9) chunked selective scan with fused dt_proj -> y (half)
    scanA<<<BATCH * NCH, 512>>>(p_xsh, p_xdbl, A_log, dt_proj_w, dt_proj_b);
    scanB<<<(BATCH * 16 * DIN) / 256, 256>>>();
    scanC<<<BATCH * NCH, 512>>>(p_xsh, p_xdbl, A_log, dt_proj_w, dt_proj_b,
                                Dv, p_xz, p_yh);

    // 10) out_proj + skip*xnorm_h -> y2 (fp32)
    hgemm_tn<2, false, 128><<<dim3(CDIM / 128, BL / 128), 256>>>(
        p_yh, DIN, p_wout, p_y2, nullptr, CDIM, BL, CDIM, DIN,
        nullptr, skip_scale, p_xnh);

    // 11) LN2 -> ln2_h
    ln_kernel<<<BL / 8, 256>>>(p_y2, ln_g, ln_b, p_ln2h, BL);

    // 12) proj + bias -> out
    hgemm_tn<3, false, 128><<<dim3(CDIM / 128, BL / 128), 256>>>(
        p_ln2h, CDIM, p_wpr, out, nullptr, CDIM, BL, CDIM, CDIM,
        proj_b, nullptr, nullptr);
}

// round 14
// speedup vs baseline: 1.4307x; 1.4307x over previous
#include <cuda_runtime.h>
#include <cuda_fp16.h>
#include <stdint.h>
#include <math.h>

// ---------------- problem constants ----------------
#define BATCH   4
#define LSEQ    16384            // H*W
#define BL      65536            // BATCH*LSEQ
#define CDIM    256
#define DIN     512              // d_inner
#define DSTATE  16
#define DTRANK  16
#define XDBL    48               // dt_rank + 2*d_state
#define NCH     128              // scan chunks per sequence
#define CHUNK   128              // LSEQ / NCH

typedef unsigned long long ull;

// ---------------- scratch (static device globals) ---------------------------
__device__ __half g_xnorm_h[(size_t)BL * CDIM];
__device__ __half g_xz    [(size_t)BL * 2 * DIN];
__device__ __half g_xs_h  [(size_t)BL * DIN];
__device__ float  g_xdbl  [(size_t)BL * XDBL];
__device__ __half g_y_h   [(size_t)BL * DIN];
__device__ __half g_y2h   [(size_t)BL * CDIM];
__device__ __half g_ln2_h [(size_t)BL * CDIM];
__device__ float  g_agg   [(size_t)BATCH * NCH * 32 * DIN];
__device__ float  g_hinit [(size_t)BATCH * NCH * 16 * DIN];
__device__ __half g_w_in  [2 * DIN * CDIM];
__device__ __half g_w_xp  [XDBL * DIN];
__device__ __half g_w_out [CDIM * DIN];
__device__ __half g_w_pr  [CDIM * CDIM];

// ---------------- f32x2 packed helpers (sm_100+) -----------------------------
__device__ __forceinline__ ull f2x2_pack(float lo, float hi) {
    ull r; asm("mov.b64 %0, {%1, %2};" : "=l"(r) : "f"(lo), "f"(hi)); return r;
}
__device__ __forceinline__ void f2x2_unpack(ull v, float& lo, float& hi) {
    asm("mov.b64 {%0, %1}, %2;" : "=f"(lo), "=f"(hi) : "l"(v));
}
__device__ __forceinline__ ull f2x2_mul(ull a, ull b) {
    ull r; asm("mul.rn.f32x2 %0, %1, %2;" : "=l"(r) : "l"(a), "l"(b)); return r;
}
__device__ __forceinline__ ull f2x2_fma(ull a, ull b, ull c) {
    ull r; asm("fma.rn.f32x2 %0, %1, %2, %3;" : "=l"(r) : "l"(a), "l"(b), "l"(c)); return r;
}

// ---------------- async-copy / ldmatrix helpers ------------------------------
__device__ __forceinline__ void cp_async16(uint32_t dst, const void* src, bool pred) {
    int sz = pred ? 16 : 0;
    asm volatile("cp.async.cg.shared.global [%0], [%1], 16, %2;\n"
                 :: "r"(dst), "l"(src), "r"(sz));
}
__device__ __forceinline__ void cp_commit()  { asm volatile("cp.async.commit_group;\n"); }
__device__ __forceinline__ void cp_wait1()   { asm volatile("cp.async.wait_group 1;\n"); }

__device__ __forceinline__ void ldsm_x4(unsigned& r0, unsigned& r1,
                                        unsigned& r2, unsigned& r3, uint32_t addr) {
    asm volatile("ldmatrix.sync.aligned.m8n8.x4.shared.b16 {%0,%1,%2,%3}, [%4];"
                 : "=r"(r0), "=r"(r1), "=r"(r2), "=r"(r3) : "r"(addr));
}

__device__ __forceinline__ void mma_fp16(float* d, const unsigned* a, const unsigned* b) {
    asm volatile(
        "mma.sync.aligned.m16n8k16.row.col.f32.f16.f16.f32 "
        "{%0,%1,%2,%3}, {%4,%5,%6,%7}, {%8,%9}, {%0,%1,%2,%3};\n"
        : "+f"(d[0]), "+f"(d[1]), "+f"(d[2]), "+f"(d[3])
        : "r"(a[0]), "r"(a[1]), "r"(a[2]), "r"(a[3]),
          "r"(b[0]), "r"(b[1]));
}

// ---------------- dummy (launch-order shim for ncu slot) ---------------------
__global__ void dummy_kernel() {
    if (blockIdx.x == 0 && threadIdx.x == 0) g_agg[0] = 0.f;  // overwritten by scanA
}

// ---------------- one-shot weight convert (all 4 fp16 weights) --------------
#define F4_IN   (2 * DIN * CDIM / 4)
#define F4_XP   (XDBL * DIN / 4)
#define F4_OUT  (CDIM * DIN / 4)
#define F4_PR   (CDIM * CDIM / 4)
#define F4_TOT  (F4_IN + F4_XP + F4_OUT + F4_PR)

__global__ void wcvt_kernel(const float* __restrict__ w_in, const float* __restrict__ w_xp,
                            const float* __restrict__ w_out, const float* __restrict__ w_pr)
{
    int i = blockIdx.x * blockDim.x + threadIdx.x;
    if (i >= F4_TOT) return;
    const float* src; __half* dst; int j = i;
    if (j < F4_IN)                  { src = w_in;  dst = g_w_in; }
    else if ((j -= F4_IN) < F4_XP)  { src = w_xp;  dst = g_w_xp; }
    else if ((j -= F4_XP) < F4_OUT) { src = w_out; dst = g_w_out; }
    else { j -= F4_OUT;               src = w_pr;  dst = g_w_pr; }
    float4 v = reinterpret_cast<const float4*>(src)[j];
    __half2 h0 = __floats2half2_rn(v.x, v.y);
    __half2 h1 = __floats2half2_rn(v.z, v.w);
    uint2 u;
    u.x = *reinterpret_cast<unsigned*>(&h0);
    u.y = *reinterpret_cast<unsigned*>(&h1);
    reinterpret_cast<uint2*>(dst)[j] = u;
}

// ---------------- LayerNorm (C=256), one warp per row, half output ----------
// IN_HALF: input buffer is __half (else float)
template <bool IN_HALF>
__global__ __launch_bounds__(256)
void ln_kernel(const void* __restrict__ xin, const float* __restrict__ g,
               const float* __restrict__ bta, __half* __restrict__ outh, int nrows)
{
    int warp = (blockIdx.x * blockDim.x + threadIdx.x) >> 5;
    int lane = threadIdx.x & 31;
    if (warp >= nrows) return;
    int c0 = lane * 8;
    float v[8];
    if (IN_HALF) {
        const __half* xr = (const __half*)xin + (size_t)warp * CDIM + c0;
        uint4 u = *reinterpret_cast<const uint4*>(xr);
        float2 f0 = __half22float2(*reinterpret_cast<__half2*>(&u.x));
        float2 f1 = __half22float2(*reinterpret_cast<__half2*>(&u.y));
        float2 f2 = __half22float2(*reinterpret_cast<__half2*>(&u.z));
        float2 f3 = __half22float2(*reinterpret_cast<__half2*>(&u.w));
        v[0]=f0.x; v[1]=f0.y; v[2]=f1.x; v[3]=f1.y;
        v[4]=f2.x; v[5]=f2.y; v[6]=f3.x; v[7]=f3.y;
    } else {
        const float* xr = (const float*)xin + (size_t)warp * CDIM + c0;
        float4 va = *reinterpret_cast<const float4*>(xr);
        float4 vb = *reinterpret_cast<const float4*>(xr + 4);
        v[0]=va.x; v[1]=va.y; v[2]=va.z; v[3]=va.w;
        v[4]=vb.x; v[5]=vb.y; v[6]=vb.z; v[7]=vb.w;
    }
    float s = 0.f, s2 = 0.f;
#pragma unroll
    for (int j = 0; j < 8; j++) { s += v[j]; s2 += v[j] * v[j]; }
#pragma unroll
    for (int off = 16; off; off >>= 1) {
        s  += __shfl_xor_sync(0xffffffffu, s,  off);
        s2 += __shfl_xor_sync(0xffffffffu, s2, off);
    }
    float mu   = s * (1.f / CDIM);
    float var  = s2 * (1.f / CDIM) - mu * mu;
    float rstd = rsqrtf(var + 1e-5f);
    float4 ga = *reinterpret_cast<const float4*>(g + c0);
    float4 gb = *reinterpret_cast<const float4*>(g + c0 + 4);
    float4 ba = *reinterpret_cast<const float4*>(bta + c0);
    float4 bb = *reinterpret_cast<const float4*>(bta + c0 + 4);
    float o[8];
    o[0] = (v[0] - mu) * rstd * ga.x + ba.x;
    o[1] = (v[1] - mu) * rstd * ga.y + ba.y;
    o[2] = (v[2] - mu) * rstd * ga.z + ba.z;
    o[3] = (v[3] - mu) * rstd * ga.w + ba.w;
    o[4] = (v[4] - mu) * rstd * gb.x + bb.x;
    o[5] = (v[5] - mu) * rstd * gb.y + bb.y;
    o[6] = (v[6] - mu) * rstd * gb.z + bb.z;
    o[7] = (v[7] - mu) * rstd * gb.w + bb.w;
    __half2 h0 = __floats2half2_rn(o[0], o[1]);
    __half2 h1 = __floats2half2_rn(o[2], o[3]);
    __half2 h2 = __floats2half2_rn(o[4], o[5]);
    __half2 h3 = __floats2half2_rn(o[6], o[7]);
    uint4 u;
    u.x = *reinterpret_cast<unsigned*>(&h0);
    u.y = *reinterpret_cast<unsigned*>(&h1);
    u.z = *reinterpret_cast<unsigned*>(&h2);
    u.w = *reinterpret_cast<unsigned*>(&h3);
    *reinterpret_cast<uint4*>(outh + (size_t)warp * CDIM + c0) = u;
}

// ---------------- fp16 tensor-core GEMM: out = A(MxK,lda) @ W(NxK)^T -------
// ROUND-12 known-good: BM=128, BK=32, 3-stage cp.async pipeline, 2 barriers/iter.
// 8 warps = 4M x 2N; 2 CTAs/SM.
// EPI: 0 plain | 1 softplus(v+p1[n]) | 2 v+p2[0]*half(p1h[m*ldc+n]) | 3 v+p1[n]
template <int EPI, bool HOUT, int BN_>
__global__ __launch_bounds__(256, 2)
void hgemm_tn(const __half* __restrict__ A, int lda,
              const __half* __restrict__ W,
              float* __restrict__ Cf, __half* __restrict__ Ch, int ldc,
              int M, int N, int K,
              const float* __restrict__ p1, const float* __restrict__ p2,
              const __half* __restrict__ p1h)
{
    constexpr int BM = 128, BK = 32, LDP = 40;   // 40 halfs = 80B row stride
    constexpr int NT = BN_ / 16;
    constexpr int ABUF = BM * LDP * 2;           // bytes per A stage
    constexpr int BBUF = BN_ * LDP * 2;
    __shared__ __half As[3][BM][LDP];
    __shared__ __half Bs[3][BN_][LDP];

    const int t    = threadIdx.x;
    const int wid  = t >> 5;
    const int lane = t & 31;
    const int wm   = wid >> 1;           // 0..3 (32 rows each)
    const int wn   = wid & 1;            // 0..1 (BN_/2 cols each)
    const int row0 = blockIdx.y * BM;
    const int col0 = blockIdx.x * BN_;

    float acc[2][NT][4];
#pragma unroll
    for (int i = 0; i < 2; i++)
#pragma unroll
        for (int j = 0; j < NT; j++)
#pragma unroll
            for (int q = 0; q < 4; q++) acc[i][j][q] = 0.f;

    const int KT = K / BK;
    const __half* Arow = A + (size_t)(row0 + (t >> 1)) * lda + (t & 1) * 16;
    const bool bact    = (BN_ == 128) || (t < 128);
    const int  wrow    = col0 + (t >> 1);
    const bool wv      = bact && (wrow < N);
    const __half* Wrow = W + (size_t)(wv ? wrow : 0) * K + (t & 1) * 16;

    uint32_t sA = (uint32_t)__cvta_generic_to_shared(&As[0][0][0]);
    uint32_t sB = (uint32_t)__cvta_generic_to_shared(&Bs[0][0][0]);
    uint32_t dA0 = sA + ((t >> 1) * LDP + (t & 1) * 16) * 2;
    uint32_t dB0 = sB + ((t >> 1) * LDP + (t & 1) * 16) * 2;

    const int lr8 = lane & 7;
    uint32_t aoff = (uint32_t)(((wm * 32 + ((lane >> 3) & 1) * 8 + lr8) * LDP
                                + (lane >> 4) * 8) * 2);
    uint32_t boff = (uint32_t)(((wn * (BN_ / 2) + (lane >> 4) * 8 + lr8) * LDP
                                + ((lane >> 3) & 1) * 8) * 2);

    // prologue: stage 0 and 1
#pragma unroll
    for (int s = 0; s < 2; s++) {
        if (s < KT) {
            int k0 = s * BK;
            cp_async16(dA0 + s * ABUF, Arow + k0, true);
            cp_async16(dA0 + s * ABUF + 16, Arow + k0 + 8, true);
            if (bact) {
                cp_async16(dB0 + s * BBUF, Wrow + k0, wv);
                cp_async16(dB0 + s * BBUF + 16, Wrow + k0 + 8, wv);
            }
        }
        cp_commit();
    }

    for (int kt = 0; kt < KT; kt++) {
        cp_wait1();
        __syncthreads();
        // issue stage kt+2 (always commit to advance group numbering)
        if (kt + 2 < KT) {
            int st = (kt + 2) % 3;
            int k0 = (kt + 2) * BK;
            cp_async16(dA0 + st * ABUF, Arow + k0, true);
            cp_async16(dA0 + st * ABUF + 16, Arow + k0 + 8, true);
            if (bact) {
                cp_async16(dB0 + st * BBUF, Wrow + k0, wv);
                cp_async16(dB0 + st * BBUF + 16, Wrow + k0 + 8, wv);
            }
        }
        cp_commit();

        const int cur = kt % 3;
        uint32_t baseA = sA + cur * ABUF + aoff;
        uint32_t baseB = sB + cur * BBUF + boff;
#pragma unroll
        for (int ks = 0; ks < 2; ks++) {   // two k16 sub-steps
            uint32_t ko = ks * 16 * 2;
            unsigned af[2][4];
#pragma unroll
            for (int mt = 0; mt < 2; mt++)
                ldsm_x4(af[mt][0], af[mt][1], af[mt][2], af[mt][3],
                        baseA + mt * 16 * LDP * 2 + ko);
            unsigned bf[NT][2];
#pragma unroll
            for (int p = 0; p < NT / 2; p++)
                ldsm_x4(bf[2 * p][0], bf[2 * p][1], bf[2 * p + 1][0], bf[2 * p + 1][1],
                        baseB + p * 16 * LDP * 2 + ko);
#pragma unroll
            for (int mt = 0; mt < 2; mt++)
#pragma unroll
                for (int nt = 0; nt < NT; nt++)
                    mma_fp16(acc[mt][nt], af[mt], bf[nt]);
        }
        __syncthreads();
    }

    const int c = lane & 3;
    const int g = lane >> 2;
#pragma unroll
    for (int mt = 0; mt < 2; mt++) {
        int mrow = row0 + wm * 32 + mt * 16 + g;
#pragma unroll
        for (int nt = 0; nt < NT; nt++) {
            int n = col0 + wn * (BN_ / 2) + nt * 8 + 2 * c;
#pragma unroll
            for (int half = 0; half < 2; half++) {
                int m = mrow + half * 8;
                float vv[2];
#pragma unroll
                for (int e = 0; e < 2; e++) {
                    int nn = n + e;
                    float v = acc[mt][nt][half * 2 + e];
                    if (EPI == 1) {
                        v += p1[nn < N ? nn : 0];
                        v = (v > 20.f) ? v : log1pf(__expf(v));
                    } else if (EPI == 2) {
                        v += p2[0] * __half2float(p1h[(size_t)m * ldc + (nn < N ? nn : 0)]);
                    } else if (EPI == 3) {
                        v += p1[nn < N ? nn : 0];
                    }
                    vv[e] = v;
                }
                if (HOUT) {
                    if (n + 1 < N) {
                        __half2 hh = __floats2half2_rn(vv[0], vv[1]);
                        *reinterpret_cast<unsigned*>(&Ch[(size_t)m * ldc + n]) =
                            *reinterpret_cast<unsigned*>(&hh);
                    }
                } else {
#pragma unroll
                    for (int e = 0; e < 2; e++)
                        if (n + e < N) Cf[(size_t)m * ldc + n + e] = vv[e];
                }
            }
        }
    }
}

// ---------------- causal depthwise conv (k=4) + SiLU, 8 timesteps/thread ----
__global__ __launch_bounds__(256)
void conv_silu_kernel(const __half* __restrict__ xz, const float* __restrict__ cw,
                      const float* __restrict__ cb, __half* __restrict__ xsh)
{
    int idx  = blockIdx.x * blockDim.x + threadIdx.x;
    int dv   = (idx & 127) * 4;
    int rg   = idx >> 7;
    int row0 = rg * 8;
    int l0   = row0 & (LSEQ - 1);

    float4 cb4 = *reinterpret_cast<const float4*>(cb + dv);
    float4 cwj[4];
#pragma unroll
    for (int j = 0; j < 4; j++)
        cwj[j] = *reinterpret_cast<const float4*>(cw + (dv + j) * 4);

    __half2 vx[11][2];
#pragma unroll
    for (int k = 0; k < 11; k++) {
        int ls = l0 - 3 + k;
        if (ls >= 0) {
            uint2 u = *reinterpret_cast<const uint2*>(
                xz + (size_t)(row0 - 3 + k) * (2 * DIN) + dv);
            vx[k][0] = *reinterpret_cast<__half2*>(&u.x);
            vx[k][1] = *reinterpret_cast<__half2*>(&u.y);
        } else {
            vx[k][0] = __float2half2_rn(0.f);
            vx[k][1] = __float2half2_rn(0.f);
        }
    }

#pragma unroll
    for (int tt = 0; tt < 8; tt++) {
        float a0 = cb4.x, a1 = cb4.y, a2 = cb4.z, a3 = cb4.w;
#pragma unroll
        for (int k = 0; k < 4; k++) {
            float2 f0 = __half22float2(vx[tt + k][0]);
            float2 f1 = __half22float2(vx[tt + k][1]);
            a0 = fmaf((&cwj[0].x)[k], f0.x, a0);
            a1 = fmaf((&cwj[1].x)[k], f0.y, a1);
            a2 = fmaf((&cwj[2].x)[k], f1.x, a2);
            a3 = fmaf((&cwj[3].x)[k], f1.y, a3);
        }
        a0 = a0 / (1.f + __expf(-a0));
        a1 = a1 / (1.f + __expf(-a1));
        a2 = a2 / (1.f + __expf(-a2));
        a3 = a3 / (1.f + __expf(-a3));
        __half2 h0 = __floats2half2_rn(a0, a1);
        __half2 h1 = __floats2half2_rn(a2, a3);
        uint2 u;
        u.x = *reinterpret_cast<unsigned*>(&h0);
        u.y = *reinterpret_cast<unsigned*>(&h1);
        *reinterpret_cast<uint2*>(xsh + (size_t)(row0 + tt) * DIN + dv) = u;
    }
}

// ---------------- fused delta helpers ----------------------------------------
__device__ __forceinline__ void delta_r(float v, float& delta, float& r) {
    if (v > 15.f) { delta = v; r = __expf(-v); }
    else {
        float tt = __expf(v);
        delta = __logf(1.f + tt);
        r = __fdividef(1.f, 1.f + tt);
    }
}
// packed pow chain: dA2[k] = {r^(2k+1), r^(2k+2)}
__device__ __forceinline__ void pow_chain2(float r, ull* dA2) {
    float r2 = r * r;
    dA2[0] = f2x2_pack(r, r2);
    ull rr = f2x2_pack(r2, r2);
#pragma unroll
    for (int k = 1; k < 8; k++) dA2[k] = f2x2_mul(dA2[k - 1], rr);
}

// ---------------- scan pass A ------------------------------------------------
__global__ __launch_bounds__(512)
void scanA(const __half* __restrict__ xs, const float* __restrict__ xdbl,
           const float* __restrict__ A_log,
           const float* __restrict__ dtw, const float* __restrict__ dtb)
{
    __shared__ __align__(16) float sD[CHUNK][32];
    int d  = threadIdx.x;
    int ch = blockIdx.x & (NCH - 1);
    int b  = blockIdx.x >> 7;
    int rowbase = b * LSEQ + ch * CHUNK;

    for (int i = threadIdx.x; i < CHUNK * 32; i += 512) {
        int tt = i >> 5, j = i & 31;
        sD[tt][j] = xdbl[(size_t)(rowbase + tt) * XDBL + j];
    }
    __syncthreads();

    float Ad[DSTATE];
    bool fastA = true;
#pragma unroll
    for (int n = 0; n < DSTATE; n++) {
        Ad[n] = -__expf(A_log[d * DSTATE + n]);
        fastA = fastA && (fabsf(Ad[n] + (float)(n + 1)) < 1e-3f * (n + 1));
    }
    ull w2[8];
#pragma unroll
    for (int j = 0; j < 8; j++)
        w2[j] = f2x2_pack(dtw[d * DTRANK + 2 * j], dtw[d * DTRANK + 2 * j + 1]);
    float bias = dtb[d];

    const __half* up = xs + (size_t)rowbase * DIN + d;
    float dlsum = 0.f;

    if (fastA) {
        ull h2[8];
#pragma unroll
        for (int k = 0; k < 8; k++) h2[k] = f2x2_pack(0.f, 0.f);
        float ub[4];
#pragma unroll
        for (int q = 0; q < 4; q++) ub[q] = __half2float(up[(size_t)q * DIN]);
        for (int t0 = 0; t0 < CHUNK; t0 += 4) {
#pragma unroll
            for (int q = 0; q < 4; q++) {
                int t = t0 + q;
                float u = ub[q];
                if (t + 4 < CHUNK) ub[q] = __half2float(up[(size_t)(t + 4) * DIN]);
                const ull* row = reinterpret_cast<const ull*>(&sD[t][0]);
                ull v2 = f2x2_mul(row[0], w2[0]);
#pragma unroll
                for (int j = 1; j < 8; j++) v2 = f2x2_fma(row[j], w2[j], v2);
                float vl, vh;
                f2x2_unpack(v2, vl, vh);
                float v = vl + vh + bias;
                float delta, r;
                delta_r(v, delta, r);
                float du = delta * u;
                dlsum += delta;
                ull dA2[8];
                pow_chain2(r, dA2);
                ull du2 = f2x2_pack(du, du);
                const ull* B2 = row + 8;
#pragma unroll
                for (int k = 0; k < 8; k++)
                    h2[k] = f2x2_fma(dA2[k], h2[k], f2x2_mul(du2, B2[k]));
            }
        }
        size_t base = ((size_t)(b * NCH + ch) * 32) * DIN + d;
        float R = __expf(-dlsum);
        ull aP2[8];
        pow_chain2(R, aP2);
#pragma unroll
        for (int k = 0; k < 8; k++) {
            float al, ah, hl, hh;
            f2x2_unpack(aP2[k], al, ah);
            f2x2_unpack(h2[k], hl, hh);
            g_agg[base + (size_t)(2 * k) * DIN]          = al;
            g_agg[base + (size_t)(2 * k + 1) * DIN]      = ah;
            g_agg[base + (size_t)(16 + 2 * k) * DIN]     = hl;
            g_agg[base + (size_t)(16 + 2 * k + 1) * DIN] = hh;
        }
    } else {
        float h[DSTATE];
#pragma unroll
        for (int n = 0; n < DSTATE; n++) h[n] = 0.f;
        float u = __half2float(up[0]);
        for (int t = 0; t < CHUNK; t++) {
            float un = (t + 1 < CHUNK) ? __half2float(up[(size_t)(t + 1) * DIN]) : 0.f;
            float v = bias;
#pragma unroll
            for (int j = 0; j < DTRANK; j++) v = fmaf(sD[t][j], dtw[d * DTRANK + j], v);
            float delta, r;
            delta_r(v, delta, r);
            float du = delta * u;
            dlsum += delta;
#pragma unroll
            for (int n = 0; n < DSTATE; n++) {
                float dA = __expf(delta * Ad[n]);
                h[n] = fmaf(dA, h[n], du * sD[t][16 + n]);
            }
            u = un;
        }
        size_t base = ((size_t)(b * NCH + ch) * 32) * DIN + d;
#pragma unroll
        for (int n = 0; n < DSTATE; n++) {
            g_agg[base + (size_t)n * DIN]        = __expf(dlsum * Ad[n]);
            g_agg[base + (size_t)(16 + n) * DIN] = h[n];
        }
    }
}

// ---------------- scan pass B ------------------------------------------------
__global__ __launch_bounds__(256)
void scanB()
{
    int tid = blockIdx.x * blockDim.x + threadIdx.x;
    int d = tid & (DIN - 1);
    int n = (tid >> 9) & 15;
    int b = tid >> 13;
    float h = 0.f;
    for (int ch = 0; ch < NCH; ch++) {
        size_t base = (size_t)(b * NCH + ch);
        g_hinit[(base * 16 + n) * DIN + d] = h;
        float a = g_agg[(base * 32 + n) * DIN + d];
        float s = g_agg[(base * 32 + 16 + n) * DIN + d];
        h = fmaf(a, h, s);
    }
}

// ---------------- scan pass C ------------------------------------------------
__global__ __launch_bounds__(512)
void scanC(const __half* __restrict__ xs, const float* __restrict__ xdbl,
           const float* __restrict__ A_log,
           const float* __restrict__ dtw, const float* __restrict__ dtb,
           const float* __restrict__ Dv, const __half* __restrict__ xz,
           __half* __restrict__ yout)
{
    __shared__ __align__(16) float sD[CHUNK][XDBL];
    int d  = threadIdx.x;
    int ch = blockIdx.x & (NCH - 1);
    int b  = blockIdx.x >> 7;
    int rowbase = b * LSEQ + ch * CHUNK;

    for (int i = threadIdx.x; i < CHUNK * XDBL; i += 512) {
        int tt = i / XDBL, j = i % XDBL;
        sD[tt][j] = xdbl[(size_t)(rowbase + tt) * XDBL + j];
    }
    __syncthreads();

    float Ad[DSTATE];
    bool fastA = true;
#pragma unroll
    for (int n = 0; n < DSTATE; n++) {
        Ad[n] = -__expf(A_log[d * DSTATE + n]);
        fastA = fastA && (fabsf(Ad[n] + (float)(n + 1)) < 1e-3f * (n + 1));
    }
    ull w2[8];
#pragma unroll
    for (int j = 0; j < 8; j++)
        w2[j] = f2x2_pack(dtw[d * DTRANK + 2 * j], dtw[d * DTRANK + 2 * j + 1]);
    float bias = dtb[d];
    float Dd = Dv[d];
    size_t hib = ((size_t)(b * NCH + ch) * 16) * DIN + d;

    const __half* up = xs + (size_t)rowbase * DIN + d;
    const __half* zp = xz + (size_t)rowbase * (2 * DIN) + DIN + d;
    __half*       yp = yout + (size_t)rowbase * DIN + d;

    if (fastA) {
        ull h2[8];
#pragma unroll
        for (int k = 0; k < 8; k++)
            h2[k] = f2x2_pack(g_hinit[hib + (size_t)(2 * k) * DIN],
                              g_hinit[hib + (size_t)(2 * k + 1) * DIN]);
        float ub[4], zb[4];
#pragma unroll
        for (int q = 0; q < 4; q++) {
            ub[q] = __half2float(up[(size_t)q * DIN]);
            zb[q] = __half2float(zp[(size_t)q * (2 * DIN)]);
        }
        for (int t0 = 0; t0 < CHUNK; t0 += 4) {
#pragma unroll
            for (int q = 0; q < 4; q++) {
                int t = t0 + q;
                float u = ub[q], z = zb[q];
                if (t + 4 < CHUNK) {
                    ub[q] = __half2float(up[(size_t)(t + 4) * DIN]);
                    zb[q] = __half2float(zp[(size_t)(t + 4) * (2 * DIN)]);
                }
                const ull* row = reinterpret_cast<const ull*>(&sD[t][0]);
                ull v2 = f2x2_mul(row[0], w2[0]);
#pragma unroll
                for (int j = 1; j < 8; j++) v2 = f2x2_fma(row[j], w2[j], v2);
                float vl, vh;
                f2x2_unpack(v2, vl, vh);
                float v = vl + vh + bias;
                float delta, r;
                delta_r(v, delta, r);
                float du = delta * u;
                ull dA2[8];
                pow_chain2(r, dA2);
                ull du2 = f2x2_pack(du, du);
                const ull* B2 = row + 8;
                const ull* C2 = row + 16;
                ull yv2 = f2x2_pack(0.f, 0.f);
#pragma unroll
                for (int k = 0; k < 8; k++) {
                    h2[k] = f2x2_fma(dA2[k], h2[k], f2x2_mul(du2, B2[k]));
                    yv2   = f2x2_fma(h2[k], C2[k], yv2);
                }
                float yl, yh;
                f2x2_unpack(yv2, yl, yh);
                float yv = yl + yh;
                float sz = z / (1.f + __expf(-z));
                yp[(size_t)t * DIN] = __float2half_rn((yv + u * Dd) * sz);
            }
        }
    } else {
        float h[DSTATE];
#pragma unroll
        for (int n = 0; n < DSTATE; n++)
            h[n] = g_hinit[hib + (size_t)n * DIN];
        float u = __half2float(up[0]);
        float z = __half2float(zp[0]);
        for (int t = 0; t < CHUNK; t++) {
            float un = 0.f, zn = 0.f;
            if (t + 1 < CHUNK) {
                un = __half2float(up[(size_t)(t + 1) * DIN]);
                zn = __half2float(zp[(size_t)(t + 1) * (2 * DIN)]);
            }
            float v = bias;
#pragma unroll
            for (int j = 0; j < DTRANK; j++) v = fmaf(sD[t][j], dtw[d * DTRANK + j], v);
            float delta, r;
            delta_r(v, delta, r);
            float du = delta * u;
            float yv = 0.f;
#pragma unroll
            for (int n = 0; n < DSTATE; n++) {
                float dA = __expf(delta * Ad[n]);
                h[n] = fmaf(dA, h[n], du * sD[t][16 + n]);
                yv   = fmaf(h[n], sD[t][32 + n], yv);
            }
            float sz = z / (1.f + __expf(-z));
            yp[(size_t)t * DIN] = __float2half_rn((yv + u * Dd) * sz);
            u = un; z = zn;
        }
    }
}

// ---------------- host launcher ---------------------------------------------
extern "C" void kernel_launch(void* const* d_in, const int* in_sizes, int n_in,
                              void* d_out, int out_size)
{
    const float* x          = (const float*)d_in[0];
    const float* ln_g       = (const float*)d_in[1];
    const float* ln_b       = (const float*)d_in[2];
    const float* in_proj_w  = (const float*)d_in[3];
    const float* conv_w     = (const float*)d_in[4];
    const float* conv_b     = (const float*)d_in[5];
    const float* x_proj_w   = (const float*)d_in[6];
    const float* dt_proj_w  = (const float*)d_in[7];
    const float* dt_proj_b  = (const float*)d_in[8];
    const float* A_log      = (const float*)d_in[9];
    const float* Dv         = (const float*)d_in[10];
    const float* out_proj_w = (const float*)d_in[11];
    const float* proj_w     = (const float*)d_in[12];
    const float* proj_b     = (const float*)d_in[13];
    const float* skip_scale = (const float*)d_in[14];
    float* out = (float*)d_out;

    float *p_xdbl;
    __half *p_xnh, *p_xz, *p_xsh, *p_yh, *p_y2h, *p_ln2h;
    __half *p_win, *p_wxp, *p_wout, *p_wpr;
    cudaGetSymbolAddress((void**)&p_xnh,  g_xnorm_h);
    cudaGetSymbolAddress((void**)&p_xz,   g_xz);
    cudaGetSymbolAddress((void**)&p_xsh,  g_xs_h);
    cudaGetSymbolAddress((void**)&p_xdbl, g_xdbl);
    cudaGetSymbolAddress((void**)&p_yh,   g_y_h);
    cudaGetSymbolAddress((void**)&p_y2h,  g_y2h);
    cudaGetSymbolAddress((void**)&p_ln2h, g_ln2_h);
    cudaGetSymbolAddress((void**)&p_win,  g_w_in);
    cudaGetSymbolAddress((void**)&p_wxp,  g_w_xp);
    cudaGetSymbolAddress((void**)&p_wout, g_w_out);
    cudaGetSymbolAddress((void**)&p_wpr,  g_w_pr);

    // 1) LN1 -> xnorm_h
    ln_kernel<false><<<BL / 8, 256>>>(x, ln_g, ln_b, p_xnh, BL);

    // 2) one-shot weight conversion
    wcvt_kernel<<<(F4_TOT + 255) / 256, 256>>>(in_proj_w, x_proj_w, out_proj_w, proj_w);

    // 3) launch-order shim so the ncu slot (4th launch) captures in_proj
    dummy_kernel<<<1, 32>>>();

    // 4) in_proj -> xz (half)
    hgemm_tn<0, true, 128><<<dim3((2 * DIN) / 128, BL / 128), 256>>>(
        p_xnh, CDIM, p_win, nullptr, p_xz, 2 * DIN, BL, 2 * DIN, CDIM,
        nullptr, nullptr, nullptr);

    // 5) conv + SiLU -> xs (half), 8 timesteps per thread
    conv_silu_kernel<<<(BL / 8) * 128 / 256, 256>>>(p_xz, conv_w, conv_b, p_xsh);

    // 6) x_proj -> xdbl (fp32, 48 cols) with BN=64 tiles
    hgemm_tn<0, false, 64><<<dim3(1, BL / 128), 256>>>(
        p_xsh, DIN, p_wxp, p_xdbl, nullptr, XDBL, BL, XDBL, DIN,
        nullptr, nullptr, nullptr);

    // 7-9) chunked selective scan with fused dt_proj -> y (half)
    scanA<<<BATCH * NCH, 512>>>(p_xsh, p_xdbl, A_log, dt_proj_w, dt_proj_b);
    scanB<<<(BATCH * 16 * DIN) / 256, 256>>>();
    scanC<<<BATCH * NCH, 512>>>(p_xsh, p_xdbl, A_log, dt_proj_w, dt_proj_b,
                                Dv, p_xz, p_yh);

    // 10) out_proj + skip*xnorm_h -> y2 (half now)
    hgemm_tn<2, true, 128><<<dim3(CDIM / 128, BL / 128), 256>>>(
        p_yh, DIN, p_wout, nullptr, p_y2h, CDIM, BL, CDIM, DIN,
        nullptr, skip_scale, p_xnh);

    // 11) LN2 (half input) -> ln2_h
    ln_kernel<true><<<BL / 8, 256>>>(p_y2h, ln_g, ln_b, p_ln2h, BL);

    // 12) proj + bias -> out
    hgemm_tn<3, false, 128><<<dim3(CDIM / 128, BL / 128), 256>>>(
        p_ln2h, CDIM, p_wpr, out, nullptr, CDIM, BL, CDIM, CDIM,
        proj_b, nullptr, nullptr);
}